// round 7
// baseline (speedup 1.0000x reference)
#include <cuda_runtime.h>
#include <cstdint>

// ActionSmoothingLoss: segmented log-softmax KL
// NVEC = (3,3,4,25,25,8), A = 68, W = 524288
// cp.async double-buffer, 1 barrier/tile, deferred distributed finalize.

#define A_DIM      68
#define NSEG       6
#define BLOCK      256
#define TILE       64
#define F4_ROW     17
#define F4_TILE    (TILE * F4_ROW)       // 1088
#define PPITCH     7                     // gcd(7,32)=1 -> conflict-free
#define MAX_BLOCKS 1024

__device__ double g_part[MAX_BLOCKS];
__device__ unsigned int g_count = 0;     // returns to 0 each call

__device__ __forceinline__ void cp16(uint32_t dst, const void* src, int bytes) {
    asm volatile("cp.async.cg.shared.global [%0], [%1], 16, %2;\n"
                 :: "r"(dst), "l"(src), "r"(bytes));
}
__device__ __forceinline__ void cp16f(uint32_t dst, const void* src) {
    asm volatile("cp.async.cg.shared.global [%0], [%1], 16;\n"
                 :: "r"(dst), "l"(src));
}
__device__ __forceinline__ void cp_commit() { asm volatile("cp.async.commit_group;\n"); }
__device__ __forceinline__ void cp_wait0()  { asm volatile("cp.async.wait_group 0;\n" ::: "memory"); }

// accumulate one element: S += e, A += e*(r - x)
#define ACC(rv, xv, S, A) { const float _r = (rv); const float _e = __expf(_r); \
                            S += _e; A = fmaf(_e, _r - (xv), A); }

__global__ void __launch_bounds__(BLOCK, 4) asl_kernel(
    const float* __restrict__ cur,
    const float* __restrict__ prev,
    float* __restrict__ out,
    int W, int ntiles, int nblocks)
{
    __shared__ float sdata[2][F4_TILE * 4];      // 2 x 17408 B
    __shared__ float spart[3][TILE * PPITCH];    // 3 x 1792 B stitch partials
    __shared__ float xs[A_DIM];
    __shared__ double wred[BLOCK / 32];
    __shared__ bool is_last;

    const int tid  = threadIdx.x;
    const int warp = tid >> 5;
    const int q    = warp >> 1;                   // quarter 0..3, warp-uniform
    const int lane = tid & 31;
    const int rt   = ((warp & 1) << 5) | lane;    // row in tile 0..63

    // --- current_action segmented log-softmax ---
    if (tid < A_DIM) xs[tid] = cur[tid];
    __syncthreads();
    if (tid < NSEG) {
        const int off[NSEG] = {0, 3, 6, 10, 35, 60};
        const int sz[NSEG]  = {3, 3, 4, 25, 25, 8};
        const int o = off[tid], n = sz[tid];
        float s = 0.f;
        for (int i = 0; i < n; i++) s += __expf(xs[o + i]);
        const float L = __logf(s);
        for (int i = 0; i < n; i++) xs[o + i] -= L;
    }
    __syncthreads();

    // --- hoist this quarter's x values into registers (elements q*16 .. q*16+15) ---
    float xr[16];
    {
        const int xb = q << 4;
        #pragma unroll
        for (int i = 0; i < 16; i++) xr[i] = xs[xb + i];
    }

    const size_t total_f4 = ((size_t)W * A_DIM) >> 2;
    const float4* gp = reinterpret_cast<const float4*>(prev);
    const uint32_t sb0 = (uint32_t)__cvta_generic_to_shared(&sdata[0][0]);
    const uint32_t sb1 = (uint32_t)__cvta_generic_to_shared(&sdata[1][0]);

    auto stage = [&](int t, uint32_t sbase) {
        const size_t base = (size_t)t * F4_TILE;
        const float4* src = gp + base + tid;
        const uint32_t dst = sbase + (uint32_t)tid * 16;
        if (base + F4_TILE <= total_f4) {              // interior: no per-cp guards
            #pragma unroll
            for (int k = 0; k < 4; k++) cp16f(dst + k * (BLOCK * 16), src + k * BLOCK);
            if (tid < F4_TILE - 4 * BLOCK) cp16f(dst + 4 * (BLOCK * 16), src + 4 * BLOCK);
        } else {
            #pragma unroll
            for (int k = 0; k < 4; k++) {
                const size_t g = base + tid + (size_t)k * BLOCK;
                cp16(dst + k * (BLOCK * 16), src + k * BLOCK, g < total_f4 ? 16 : 0);
            }
            if (tid < F4_TILE - 4 * BLOCK) {
                const size_t g = base + tid + (size_t)4 * BLOCK;
                cp16(dst + 4 * (BLOCK * 16), src + 4 * BLOCK, g < total_f4 ? 16 : 0);
            }
        }
        cp_commit();
    };

    const float INV3  = 1.f / 3.f;
    const float INV4  = 0.25f;
    const float INV25 = 1.f / 25.f;
    const float INV8  = 0.125f;

    double acc_d = 0.0;
    float c0 = 0.f, c1 = 0.f;    // carried local partials (q1: s3,a3 ; q2: s4,a4)
    int   pw  = -1;              // previous tile's row index (deferred finalize)
    int   pps = 0;               // previous tile's spart slot

    int tile = blockIdx.x;
    stage(tile, sb0);            // prologue (every block has >=1 tile)
    int cb = 0, ps = 0;

    for (; tile < ntiles; tile += nblocks) {
        cp_wait0();
        __syncthreads();          // sdata[cb] ready; spart[pps] published; safe to restage cb^1

        const int next = tile + nblocks;
        if (next < ntiles) stage(next, cb ? sb0 : sb1);

        // --- deferred finalize of previous tile (q1: seg3, q2: seg4) ---
        if (q == 1) {
            const float* pp = &spart[pps][rt * PPITCH];
            const float s3 = c0 + pp[0] + pp[2];
            const float a3 = c1 + pp[1] + pp[3];
            if (pw >= 0) acc_d += (double)(INV25 * (__fdividef(a3, s3) - __logf(s3)));
        } else if (q == 2) {
            const float* pp = &spart[pps][rt * PPITCH];
            const float s4 = c0 + pp[4];
            const float a4 = c1 + pp[5];
            if (pw >= 0) acc_d += (double)(INV25 * (__fdividef(a4, s4) - __logf(s4)));
        }

        // --- accumulate current tile ---
        const float4* rf = reinterpret_cast<const float4*>(&sdata[cb][rt * A_DIM]);
        float* pp = &spart[ps][rt * PPITCH];
        const int w = tile * TILE + rt;
        const bool valid = (w < W);

        if (q == 0) {                                  // elements 0..15: segs 0,1,2,3p
            const float4 v0 = rf[0], v1 = rf[1], v2 = rf[2], v3 = rf[3];
            float s0=0,a0=0,s1=0,a1=0,s2=0,a2=0,s3=0,a3=0;
            ACC(v0.x, xr[0],  s0, a0); ACC(v0.y, xr[1],  s0, a0); ACC(v0.z, xr[2],  s0, a0);
            ACC(v0.w, xr[3],  s1, a1); ACC(v1.x, xr[4],  s1, a1); ACC(v1.y, xr[5],  s1, a1);
            ACC(v1.z, xr[6],  s2, a2); ACC(v1.w, xr[7],  s2, a2); ACC(v2.x, xr[8],  s2, a2);
            ACC(v2.y, xr[9],  s2, a2);
            ACC(v2.z, xr[10], s3, a3); ACC(v2.w, xr[11], s3, a3); ACC(v3.x, xr[12], s3, a3);
            ACC(v3.y, xr[13], s3, a3); ACC(v3.z, xr[14], s3, a3); ACC(v3.w, xr[15], s3, a3);
            pp[0] = s3; pp[1] = a3;
            if (valid) {
                float t = INV3 * (__fdividef(a0, s0) - __logf(s0));
                t      += INV3 * (__fdividef(a1, s1) - __logf(s1));
                t      += INV4 * (__fdividef(a2, s2) - __logf(s2));
                acc_d += (double)t;
            }
        } else if (q == 1) {                           // elements 16..31: seg3
            const float4 v0 = rf[4], v1 = rf[5], v2 = rf[6], v3 = rf[7];
            float s3=0,a3=0;
            ACC(v0.x, xr[0],  s3, a3); ACC(v0.y, xr[1],  s3, a3); ACC(v0.z, xr[2],  s3, a3);
            ACC(v0.w, xr[3],  s3, a3); ACC(v1.x, xr[4],  s3, a3); ACC(v1.y, xr[5],  s3, a3);
            ACC(v1.z, xr[6],  s3, a3); ACC(v1.w, xr[7],  s3, a3); ACC(v2.x, xr[8],  s3, a3);
            ACC(v2.y, xr[9],  s3, a3); ACC(v2.z, xr[10], s3, a3); ACC(v2.w, xr[11], s3, a3);
            ACC(v3.x, xr[12], s3, a3); ACC(v3.y, xr[13], s3, a3); ACC(v3.z, xr[14], s3, a3);
            ACC(v3.w, xr[15], s3, a3);
            c0 = s3; c1 = a3;                          // carried to next iteration
        } else if (q == 2) {                           // elements 32..47: seg3p, seg4p
            const float4 v0 = rf[8], v1 = rf[9], v2 = rf[10], v3 = rf[11];
            float s3=0,a3=0,s4=0,a4=0;
            ACC(v0.x, xr[0],  s3, a3); ACC(v0.y, xr[1],  s3, a3); ACC(v0.z, xr[2],  s3, a3);
            ACC(v0.w, xr[3],  s4, a4); ACC(v1.x, xr[4],  s4, a4); ACC(v1.y, xr[5],  s4, a4);
            ACC(v1.z, xr[6],  s4, a4); ACC(v1.w, xr[7],  s4, a4); ACC(v2.x, xr[8],  s4, a4);
            ACC(v2.y, xr[9],  s4, a4); ACC(v2.z, xr[10], s4, a4); ACC(v2.w, xr[11], s4, a4);
            ACC(v3.x, xr[12], s4, a4); ACC(v3.y, xr[13], s4, a4); ACC(v3.z, xr[14], s4, a4);
            ACC(v3.w, xr[15], s4, a4);
            pp[2] = s3; pp[3] = a3;
            c0 = s4; c1 = a4;                          // carried to next iteration
        } else {                                       // elements 48..67: seg4p, seg5
            const float4 v0 = rf[12], v1 = rf[13], v2 = rf[14], v3 = rf[15], v4 = rf[16];
            float s4=0,a4=0,s5=0,a5=0;
            ACC(v0.x, xr[0],  s4, a4); ACC(v0.y, xr[1],  s4, a4); ACC(v0.z, xr[2],  s4, a4);
            ACC(v0.w, xr[3],  s4, a4); ACC(v1.x, xr[4],  s4, a4); ACC(v1.y, xr[5],  s4, a4);
            ACC(v1.z, xr[6],  s4, a4); ACC(v1.w, xr[7],  s4, a4); ACC(v2.x, xr[8],  s4, a4);
            ACC(v2.y, xr[9],  s4, a4); ACC(v2.z, xr[10], s4, a4); ACC(v2.w, xr[11], s4, a4);
            ACC(v3.x, xr[12], s5, a5); ACC(v3.y, xr[13], s5, a5); ACC(v3.z, xr[14], s5, a5);
            ACC(v3.w, xr[15], s5, a5);
            ACC(v4.x, xs[64], s5, a5); ACC(v4.y, xs[65], s5, a5); ACC(v4.z, xs[66], s5, a5);
            ACC(v4.w, xs[67], s5, a5);
            pp[4] = s4; pp[5] = a4;
            if (valid) acc_d += (double)(INV8 * (__fdividef(a5, s5) - __logf(s5)));
        }

        pw  = valid ? w : -1;
        pps = ps;
        ps  = (ps == 2) ? 0 : ps + 1;
        cb ^= 1;
    }

    // --- epilogue: finalize the last tile's deferred segments ---
    __syncthreads();
    if (q == 1) {
        const float* pp = &spart[pps][rt * PPITCH];
        const float s3 = c0 + pp[0] + pp[2];
        const float a3 = c1 + pp[1] + pp[3];
        if (pw >= 0) acc_d += (double)(INV25 * (__fdividef(a3, s3) - __logf(s3)));
    } else if (q == 2) {
        const float* pp = &spart[pps][rt * PPITCH];
        const float s4 = c0 + pp[4];
        const float a4 = c1 + pp[5];
        if (pw >= 0) acc_d += (double)(INV25 * (__fdividef(a4, s4) - __logf(s4)));
    }

    // --- block reduction (double), deterministic ---
    double d = acc_d;
    #pragma unroll
    for (int st = 16; st > 0; st >>= 1)
        d += __shfl_down_sync(0xFFFFFFFFu, d, st);
    if (lane == 0) wred[warp] = d;
    __syncthreads();
    if (tid == 0) {
        double b = 0.0;
        #pragma unroll
        for (int k = 0; k < BLOCK / 32; k++) b += wred[k];
        g_part[blockIdx.x] = b;
        __threadfence();
        unsigned int t = atomicAdd(&g_count, 1u);
        is_last = (t == (unsigned int)(nblocks - 1));
    }
    __syncthreads();

    if (is_last) {
        double a2 = 0.0;
        for (int k = tid; k < nblocks; k += BLOCK) a2 += g_part[k];
        #pragma unroll
        for (int st = 16; st > 0; st >>= 1)
            a2 += __shfl_down_sync(0xFFFFFFFFu, a2, st);
        if (lane == 0) wred[warp] = a2;
        __syncthreads();
        if (tid == 0) {
            double tot = 0.0;
            #pragma unroll
            for (int k = 0; k < BLOCK / 32; k++) tot += wred[k];
            out[0] = (float)(tot / (double)W);
            g_count = 0;
        }
    }
}

extern "C" void kernel_launch(void* const* d_in, const int* in_sizes, int n_in,
                              void* d_out, int out_size)
{
    const float* cur  = (const float*)d_in[0];   // [68]
    const float* prev = (const float*)d_in[1];   // [W, 68]
    const int W = in_sizes[1] / A_DIM;
    const int ntiles = (W + TILE - 1) / TILE;

    int nblocks = 148 * 4;                       // 4 resident blocks/SM
    if (nblocks > ntiles) nblocks = ntiles;
    if (nblocks > MAX_BLOCKS) nblocks = MAX_BLOCKS;

    asl_kernel<<<nblocks, BLOCK>>>(cur, prev, (float*)d_out, W, ntiles, nblocks);
}

// round 8
// speedup vs baseline: 1.1856x; 1.1856x over previous
#include <cuda_runtime.h>
#include <cstdint>

// ActionSmoothingLoss: segmented log-softmax KL
// NVEC = (3,3,4,25,25,8), A = 68, W = 524288
// Warp-autonomous cp.async pipeline: no block barriers in the main loop.

#define A_DIM       68
#define NSEG        6
#define BLOCK       128
#define WPB         4                   // warps per block
#define RPC         32                  // rows per chunk (one row per lane)
#define F4_CHUNK    (RPC * 17)          // 544 float4 per chunk
#define CHUNK_BYTES (F4_CHUNK * 16)     // 8704 B
#define MAX_BLOCKS  1024

__device__ double g_part[MAX_BLOCKS];
__device__ unsigned int g_count = 0;    // returns to 0 each call -> graph-replay safe

#define SEG_OF(k) ((k) < 3 ? 0 : (k) < 6 ? 1 : (k) < 10 ? 2 : (k) < 35 ? 3 : (k) < 60 ? 4 : 5)

__device__ __forceinline__ void cp16g(uint32_t dst, const void* src, int bytes) {
    asm volatile("cp.async.cg.shared.global [%0], [%1], 16, %2;\n"
                 :: "r"(dst), "l"(src), "r"(bytes));
}
__device__ __forceinline__ void cp16(uint32_t dst, const void* src) {
    asm volatile("cp.async.cg.shared.global [%0], [%1], 16;\n"
                 :: "r"(dst), "l"(src));
}
__device__ __forceinline__ void cp_commit() { asm volatile("cp.async.commit_group;\n"); }
__device__ __forceinline__ void cp_wait1()  { asm volatile("cp.async.wait_group 1;\n" ::: "memory"); }
__device__ __forceinline__ void cp_wait0()  { asm volatile("cp.async.wait_group 0;\n" ::: "memory"); }

extern __shared__ float dynsmem[];       // [WPB][2][F4_CHUNK*4] floats

__global__ void __launch_bounds__(BLOCK) asl_kernel(
    const float* __restrict__ cur,
    const float* __restrict__ prev,
    float* __restrict__ out,
    int W, int nchunks, int nblocks)
{
    __shared__ float xs[A_DIM];
    __shared__ double wred[WPB];
    __shared__ bool is_last;

    const int tid  = threadIdx.x;
    const int warp = tid >> 5;
    const int lane = tid & 31;

    // --- current_action segmented log-softmax (once per block) ---
    if (tid < A_DIM) xs[tid] = cur[tid];
    __syncthreads();
    if (tid < NSEG) {
        const int off[NSEG] = {0, 3, 6, 10, 35, 60};
        const int sz[NSEG]  = {3, 3, 4, 25, 25, 8};
        const int o = off[tid], n = sz[tid];
        float s = 0.f;
        for (int i = 0; i < n; i++) s += __expf(xs[o + i]);
        const float L = __logf(s);
        for (int i = 0; i < n; i++) xs[o + i] -= L;
    }
    __syncthreads();

    // --- warp-private double buffer in dynamic smem ---
    float* mybuf = dynsmem + (size_t)warp * (2 * F4_CHUNK * 4);
    float* bufp[2] = { mybuf, mybuf + F4_CHUNK * 4 };
    const uint32_t sb[2] = {
        (uint32_t)__cvta_generic_to_shared(bufp[0]),
        (uint32_t)__cvta_generic_to_shared(bufp[1])
    };

    const size_t total_f4 = ((size_t)W * A_DIM) >> 2;
    const float4* gp = reinterpret_cast<const float4*>(prev);

    const int total_warps = nblocks * WPB;
    const int gw = blockIdx.x * WPB + warp;

    // stage one chunk into buffer b (17 coalesced cp.async per lane)
    auto stage = [&](int chunk, int b) {
        const size_t base = (size_t)chunk * F4_CHUNK;
        const float4* src = gp + base + lane;
        const uint32_t dst = sb[b] + (uint32_t)lane * 16;
        if (base + F4_CHUNK <= total_f4) {
            #pragma unroll
            for (int k = 0; k < 17; k++) cp16(dst + k * (32 * 16), src + k * 32);
        } else {
            #pragma unroll
            for (int k = 0; k < 17; k++) {
                const size_t g = base + lane + (size_t)k * 32;
                cp16g(dst + k * (32 * 16), src + k * 32, g < total_f4 ? 16 : 0);
            }
        }
        cp_commit();
    };

    double acc_d = 0.0;

    // --- warp-local pipeline: depth 2, no block barriers ---
    int pending = 0;
    if (gw < nchunks) { stage(gw, 0); pending++; }
    if (gw + total_warps < nchunks) { stage(gw + total_warps, 1); pending++; }

    int bi = 0;
    for (int c = gw; c < nchunks; c += total_warps) {
        if (pending == 2) cp_wait1(); else cp_wait0();
        __syncwarp();

        // --- compute: one row per lane, 17 x LDS.128 (conflict-free) ---
        const int w = c * RPC + lane;
        if (w < W) {
            const float4* row = reinterpret_cast<const float4*>(bufp[bi] + lane * A_DIM);
            float s[NSEG] = {0,0,0,0,0,0};
            float a[NSEG] = {0,0,0,0,0,0};
            #pragma unroll
            for (int i = 0; i < 17; i++) {
                const float4 v = row[i];
                const float vv[4] = {v.x, v.y, v.z, v.w};
                #pragma unroll
                for (int k2 = 0; k2 < 4; k2++) {
                    const int idx = 4 * i + k2;
                    const int j = SEG_OF(idx);           // compile-time
                    const float r = vv[k2];
                    const float e = __expf(r);
                    s[j] += e;
                    a[j] = fmaf(e, r - xs[idx], a[j]);
                }
            }
            const float invn[NSEG] = {1.f/3.f, 1.f/3.f, 1.f/4.f, 1.f/25.f, 1.f/25.f, 1.f/8.f};
            float row_loss = 0.f;
            #pragma unroll
            for (int j = 0; j < NSEG; j++)
                row_loss += invn[j] * (__fdividef(a[j], s[j]) - __logf(s[j]));
            acc_d += (double)row_loss;
        }
        __syncwarp();            // all lanes done reading bufp[bi] before restage

        pending--;
        const int nxt = c + 2 * total_warps;
        if (nxt < nchunks) { stage(nxt, bi); pending++; }
        bi ^= 1;
    }

    // --- warp reduce (double), then block reduce, deterministic ---
    double d = acc_d;
    #pragma unroll
    for (int st = 16; st > 0; st >>= 1)
        d += __shfl_down_sync(0xFFFFFFFFu, d, st);
    if (lane == 0) wred[warp] = d;
    __syncthreads();
    if (tid == 0) {
        double b = 0.0;
        #pragma unroll
        for (int k = 0; k < WPB; k++) b += wred[k];
        g_part[blockIdx.x] = b;
        __threadfence();
        unsigned int t = atomicAdd(&g_count, 1u);
        is_last = (t == (unsigned int)(nblocks - 1));
    }
    __syncthreads();

    if (is_last) {
        double a2 = 0.0;
        for (int k = tid; k < nblocks; k += BLOCK) a2 += g_part[k];
        #pragma unroll
        for (int st = 16; st > 0; st >>= 1)
            a2 += __shfl_down_sync(0xFFFFFFFFu, a2, st);
        if (lane == 0) wred[warp] = a2;
        __syncthreads();
        if (tid == 0) {
            double tot = 0.0;
            #pragma unroll
            for (int k = 0; k < WPB; k++) tot += wred[k];
            out[0] = (float)(tot / (double)W);
            g_count = 0;
        }
    }
}

extern "C" void kernel_launch(void* const* d_in, const int* in_sizes, int n_in,
                              void* d_out, int out_size)
{
    const float* cur  = (const float*)d_in[0];   // [68]
    const float* prev = (const float*)d_in[1];   // [W, 68]
    const int W = in_sizes[1] / A_DIM;
    const int nchunks = (W + RPC - 1) / RPC;

    int nblocks = 148 * 3;                       // 3 blocks/SM (smem-limited)
    if (nblocks * WPB > nchunks) nblocks = (nchunks + WPB - 1) / WPB;
    if (nblocks > MAX_BLOCKS) nblocks = MAX_BLOCKS;

    const int dyn = WPB * 2 * F4_CHUNK * 16;     // 69632 B
    static int configured = 0;
    if (!configured) {
        cudaFuncSetAttribute(asl_kernel,
                             cudaFuncAttributeMaxDynamicSharedMemorySize, dyn);
        configured = 1;
    }

    asl_kernel<<<nblocks, BLOCK, dyn>>>(cur, prev, (float*)d_out, W, nchunks, nblocks);
}

// round 9
// speedup vs baseline: 1.3303x; 1.1221x over previous
#include <cuda_runtime.h>
#include <cstdint>

// ActionSmoothingLoss: segmented log-softmax KL
// NVEC = (3,3,4,25,25,8), A = 68, W = 524288
// TMA bulk (cp.async.bulk) + mbarrier 3-stage ring, 1 block/SM.

#define A_DIM        68
#define NSEG         6
#define BLOCK        256
#define RPS          256                       // rows per stage
#define STAGE_FLOATS (RPS * A_DIM)             // 17408
#define STAGE_BYTES  (STAGE_FLOATS * 4)        // 69632
#define NSTAGES      3
#define GRID_MAX     148

__device__ double g_part[GRID_MAX];
__device__ unsigned int g_count = 0;           // returns to 0 each call

#define SEG_OF(k) ((k) < 3 ? 0 : (k) < 6 ? 1 : (k) < 10 ? 2 : (k) < 35 ? 3 : (k) < 60 ? 4 : 5)

__device__ __forceinline__ uint32_t s2u(const void* p) {
    return (uint32_t)__cvta_generic_to_shared(p);
}
__device__ __forceinline__ void mbar_init(uint32_t a, uint32_t cnt) {
    asm volatile("mbarrier.init.shared.b64 [%0], %1;" :: "r"(a), "r"(cnt) : "memory");
}
__device__ __forceinline__ void mbar_expect_tx(uint32_t a, uint32_t bytes) {
    asm volatile("mbarrier.arrive.expect_tx.shared.b64 _, [%0], %1;" :: "r"(a), "r"(bytes) : "memory");
}
__device__ __forceinline__ void mbar_arrive(uint32_t a) {
    asm volatile("mbarrier.arrive.shared.b64 _, [%0];" :: "r"(a) : "memory");
}
__device__ __forceinline__ void mbar_wait(uint32_t a, uint32_t ph) {
    uint32_t done;
    do {
        asm volatile("{\n\t.reg .pred p;\n\t"
                     "mbarrier.try_wait.parity.acquire.cta.shared::cta.b64 p, [%1], %2, 0x989680;\n\t"
                     "selp.b32 %0, 1, 0, p;\n\t}"
                     : "=r"(done) : "r"(a), "r"(ph) : "memory");
    } while (!done);
}
__device__ __forceinline__ void bulk_g2s(uint32_t dst, const void* src,
                                         uint32_t bytes, uint32_t mbar) {
    asm volatile("cp.async.bulk.shared::cluster.global.mbarrier::complete_tx::bytes "
                 "[%0], [%1], %2, [%3];"
                 :: "r"(dst), "l"(src), "r"(bytes), "r"(mbar) : "memory");
}

extern __shared__ float dynsmem[];             // NSTAGES * STAGE_FLOATS

__global__ void __launch_bounds__(BLOCK, 1) asl_kernel(
    const float* __restrict__ cur,
    const float* __restrict__ prev,
    float* __restrict__ out,
    int W, int nstages_total, int nblocks)
{
    __shared__ __align__(8) uint64_t full_bar[NSTAGES];
    __shared__ __align__(8) uint64_t empty_bar[NSTAGES];
    __shared__ float xs[A_DIM];
    __shared__ double wred[BLOCK / 32];
    __shared__ bool is_last;

    const int tid  = threadIdx.x;
    const int warp = tid >> 5;
    const int lane = tid & 31;

    // --- current_action segmented log-softmax ---
    if (tid < A_DIM) xs[tid] = cur[tid];
    if (tid == 0) {
        #pragma unroll
        for (int s = 0; s < NSTAGES; s++) {
            mbar_init(s2u(&full_bar[s]), 1);
            mbar_init(s2u(&empty_bar[s]), BLOCK);
        }
    }
    __syncthreads();
    asm volatile("fence.proxy.async.shared::cta;" ::: "memory");
    if (tid < NSEG) {
        const int off[NSEG] = {0, 3, 6, 10, 35, 60};
        const int sz[NSEG]  = {3, 3, 4, 25, 25, 8};
        const int o = off[tid], n = sz[tid];
        float s = 0.f;
        for (int i = 0; i < n; i++) s += __expf(xs[o + i]);
        const float L = __logf(s);
        for (int i = 0; i < n; i++) xs[o + i] -= L;
    }
    __syncthreads();

    // my stage list: iteration j handles stage (blockIdx.x + j*nblocks)
    int myiters = 0;
    if (blockIdx.x < nstages_total)
        myiters = (nstages_total - 1 - blockIdx.x) / nblocks + 1;

    const char* gbase = reinterpret_cast<const char*>(prev);

    auto issue = [&](int j) {                   // thread 0 only
        const int stage = blockIdx.x + j * nblocks;
        const int slot  = j % NSTAGES;
        const size_t row0 = (size_t)stage * RPS;
        int rows = W - (int)row0; if (rows > RPS) rows = RPS;
        const uint32_t bytes = (uint32_t)rows * (A_DIM * 4);
        const uint32_t fb = s2u(&full_bar[slot]);
        mbar_expect_tx(fb, bytes);
        bulk_g2s(s2u(dynsmem + (size_t)slot * STAGE_FLOATS),
                 gbase + row0 * (A_DIM * 4), bytes, fb);
    };

    // prologue: fill the ring
    if (tid == 0) {
        const int np = myiters < NSTAGES ? myiters : NSTAGES;
        for (int j = 0; j < np; j++) issue(j);
    }

    double acc_d = 0.0;

    for (int j = 0; j < myiters; j++) {
        const int slot = j % NSTAGES;
        const uint32_t ph = (uint32_t)((j / NSTAGES) & 1);
        mbar_wait(s2u(&full_bar[slot]), ph);

        // --- compute: one row per thread, 17 x LDS.128 (conflict-free) ---
        const int stage = blockIdx.x + j * nblocks;
        const int w = stage * RPS + tid;
        if (w < W) {
            const float4* row = reinterpret_cast<const float4*>(
                dynsmem + (size_t)slot * STAGE_FLOATS + tid * A_DIM);
            float s[NSEG] = {0,0,0,0,0,0};
            float a[NSEG] = {0,0,0,0,0,0};
            #pragma unroll
            for (int i = 0; i < 17; i++) {
                const float4 v = row[i];
                const float vv[4] = {v.x, v.y, v.z, v.w};
                #pragma unroll
                for (int k2 = 0; k2 < 4; k2++) {
                    const int idx = 4 * i + k2;
                    const int jj = SEG_OF(idx);          // compile-time
                    const float r = vv[k2];
                    const float e = __expf(r);
                    s[jj] += e;
                    a[jj] = fmaf(e, r - xs[idx], a[jj]);
                }
            }
            const float invn[NSEG] = {1.f/3.f, 1.f/3.f, 1.f/4.f, 1.f/25.f, 1.f/25.f, 1.f/8.f};
            float row_loss = 0.f;
            #pragma unroll
            for (int jj = 0; jj < NSEG; jj++)
                row_loss += invn[jj] * (__fdividef(a[jj], s[jj]) - __logf(s[jj]));
            acc_d += (double)row_loss;
        }

        mbar_arrive(s2u(&empty_bar[slot]));

        // producer: refill this slot once everyone is done with it
        if (tid == 0 && j + NSTAGES < myiters) {
            mbar_wait(s2u(&empty_bar[slot]), ph);   // iteration j's 256 arrivals
            issue(j + NSTAGES);
        }
    }

    __syncthreads();

    // --- block reduction (double), deterministic ---
    double d = acc_d;
    #pragma unroll
    for (int st = 16; st > 0; st >>= 1)
        d += __shfl_down_sync(0xFFFFFFFFu, d, st);
    if (lane == 0) wred[warp] = d;
    __syncthreads();
    if (tid == 0) {
        double b = 0.0;
        #pragma unroll
        for (int k = 0; k < BLOCK / 32; k++) b += wred[k];
        g_part[blockIdx.x] = b;
        __threadfence();
        unsigned int t = atomicAdd(&g_count, 1u);
        is_last = (t == (unsigned int)(nblocks - 1));
    }
    __syncthreads();

    if (is_last) {
        double a2 = 0.0;
        for (int k = tid; k < nblocks; k += BLOCK) a2 += g_part[k];
        #pragma unroll
        for (int st = 16; st > 0; st >>= 1)
            a2 += __shfl_down_sync(0xFFFFFFFFu, a2, st);
        if (lane == 0) wred[warp] = a2;
        __syncthreads();
        if (tid == 0) {
            double tot = 0.0;
            #pragma unroll
            for (int k = 0; k < BLOCK / 32; k++) tot += wred[k];
            out[0] = (float)(tot / (double)W);
            g_count = 0;
        }
    }
}

extern "C" void kernel_launch(void* const* d_in, const int* in_sizes, int n_in,
                              void* d_out, int out_size)
{
    const float* cur  = (const float*)d_in[0];   // [68]
    const float* prev = (const float*)d_in[1];   // [W, 68]
    const int W = in_sizes[1] / A_DIM;
    const int nstages_total = (W + RPS - 1) / RPS;

    int nblocks = GRID_MAX;
    if (nblocks > nstages_total) nblocks = nstages_total;

    const int dyn = NSTAGES * STAGE_BYTES;       // 208896 B
    static int configured = 0;
    if (!configured) {
        cudaFuncSetAttribute(asl_kernel,
                             cudaFuncAttributeMaxDynamicSharedMemorySize, dyn);
        configured = 1;
    }

    asl_kernel<<<nblocks, BLOCK, dyn>>>(cur, prev, (float*)d_out,
                                        W, nstages_total, nblocks);
}